// round 11
// baseline (speedup 1.0000x reference)
#include <cuda_runtime.h>
#include <stdint.h>
#include <math.h>

// ---------------------------------------------------------------------------
// DepthPriorLoss — multi-kernel optimized (fast-path compaction, agg atomics).
// Inputs: d_in[0]=rendered_depth f32 [P], d_in[1]=prior_disparity f32 [P].
// Out: out[0]=loss, out[1..P]=target_inv_ren, out[1+P..2P]=prior_metric_depth.
// ---------------------------------------------------------------------------

#define P_MAX (1u << 21)
#define ITERS 1000
#define SUBN  50000
#define CB    128            // compaction blocks (contiguous chunks, order kept)

struct Sel { unsigned prefix; unsigned rank; };

__device__ float    g_xc[P_MAX];     // compacted prior_disparity (masked order)
__device__ float    g_yc[P_MAX];     // compacted target_inv_ren
__device__ unsigned g_blockCnt[CB];
__device__ unsigned g_blockOff[CB];
__device__ unsigned g_numPts;
__device__ unsigned g_interp;
__device__ unsigned g_hist[10][2048];
__device__ Sel      g_sel[4];
__device__ float    g_medv[4];
__device__ float    g_med;
__device__ float    g_dyn;
__device__ float    g_xs[SUBN];
__device__ float    g_ys[SUBN];
__device__ float    g_scales[ITERS];
__device__ float    g_shifts[ITERS];
__device__ int      g_counts[ITERS];
__device__ float    g_s, g_t;
__device__ float    g_partial[1024];

// ---------------------------- Threefry-2x32 --------------------------------
__host__ __device__ __forceinline__
void tf2x32(unsigned k0, unsigned k1, unsigned c0, unsigned c1,
            unsigned& o0, unsigned& o1) {
    unsigned ks2 = k0 ^ k1 ^ 0x1BD11BDAu;
    unsigned x0 = c0 + k0;
    unsigned x1 = c1 + k1;
#define TF_RND(r) { x0 += x1; x1 = (x1 << (r)) | (x1 >> (32 - (r))); x1 ^= x0; }
    TF_RND(13) TF_RND(15) TF_RND(26) TF_RND(6)
    x0 += k1;  x1 += ks2 + 1u;
    TF_RND(17) TF_RND(29) TF_RND(16) TF_RND(24)
    x0 += ks2; x1 += k0 + 2u;
    TF_RND(13) TF_RND(15) TF_RND(26) TF_RND(6)
    x0 += k0;  x1 += k1 + 3u;
    TF_RND(17) TF_RND(29) TF_RND(16) TF_RND(24)
    x0 += k1;  x1 += ks2 + 4u;
    TF_RND(13) TF_RND(15) TF_RND(26) TF_RND(6)
    x0 += ks2; x1 += k0 + 5u;
#undef TF_RND
    o0 = x0; o1 = x1;
}

__device__ __forceinline__ unsigned rnd_bits(unsigned k0, unsigned k1, unsigned f) {
    unsigned o0, o1;
    tf2x32(k0, k1, 0u, f, o0, o1);
    return o0 ^ o1;
}

__device__ __forceinline__ unsigned randint_combine(unsigned hi, unsigned lo,
                                                    unsigned span) {
    unsigned mult = 65536u % span;
    mult = (mult * mult) % span;                       // u32 wrap then mod (lax)
    unsigned off = (hi % span) * mult + (lo % span);   // u32 wrap (lax)
    return off % span;
}

// ------------------------------ helpers ------------------------------------
__device__ __forceinline__ bool maskf(float d) {
    return (d > 0.1f) && (d < 100.0f) && isfinite(d);
}
__device__ __forceinline__ float invren(float d) { return 1.0f / (d + 1e-6f); }

__device__ __forceinline__ unsigned ordkey(float v) {
    unsigned u = __float_as_uint(v);
    return (u & 0x80000000u) ? ~u : (u | 0x80000000u);
}
__device__ __forceinline__ float ordval(unsigned o) {
    unsigned u = (o & 0x80000000u) ? (o & 0x7FFFFFFFu) : ~o;
    return __uint_as_float(u);
}

// warp-aggregated smem histogram add (activemask-safe)
__device__ __forceinline__ void aggAdd(unsigned* h, unsigned bin) {
    unsigned am = __activemask();
    unsigned mk = __match_any_sync(am, bin);
    unsigned leader = __ffs(mk) - 1u;
    if ((threadIdx.x & 31u) == leader) atomicAdd(&h[bin], (unsigned)__popc(mk));
}

// block-wide inclusive scan (1024 threads, 2 syncs), ws = smem[32]
__device__ __forceinline__ unsigned blockScanIncl(unsigned v, unsigned* ws) {
    int lane = threadIdx.x & 31, wid = threadIdx.x >> 5;
    for (int o = 1; o < 32; o <<= 1) {
        unsigned x = __shfl_up_sync(0xffffffffu, v, o);
        if (lane >= o) v += x;
    }
    if (lane == 31) ws[wid] = v;
    __syncthreads();
    if (wid == 0) {
        unsigned s = ws[lane];
        for (int o = 1; o < 32; o <<= 1) {
            unsigned x = __shfl_up_sync(0xffffffffu, s, o);
            if (lane >= o) s += x;
        }
        ws[lane] = s;
    }
    __syncthreads();
    return v + (wid ? ws[wid - 1] : 0u);
}

// ------------------------------ kernels ------------------------------------
__global__ void initK() {
    int i = blockIdx.x * blockDim.x + threadIdx.x;
    if (i < 10 * 2048) ((unsigned*)g_hist)[i] = 0u;
    if (i < ITERS) g_counts[i] = 0;
}

// per-block mask counts over contiguous chunks (float4)
__global__ void maskCountK(const float* __restrict__ ren, int P, int ch) {
    int b = blockIdx.x, t = threadIdx.x;
    int lane = t & 31, wid = t >> 5;
    __shared__ unsigned ws[32];
    int base0 = b * ch;
    int elems = P - base0; if (elems > ch) elems = ch; if (elems < 0) elems = 0;
    int e4 = elems >> 2;
    const float4* r4 = (const float4*)(ren + base0);
    unsigned c = 0;
    for (int j = t; j < e4; j += 1024) {
        float4 d = r4[j];
        c += (maskf(d.x) ? 1u : 0u) + (maskf(d.y) ? 1u : 0u)
           + (maskf(d.z) ? 1u : 0u) + (maskf(d.w) ? 1u : 0u);
    }
    if (t < (elems & 3) && maskf(ren[base0 + (e4 << 2) + t])) c++;
    for (int o = 16; o > 0; o >>= 1) c += __shfl_down_sync(0xffffffffu, c, o);
    if (lane == 0) ws[wid] = c;
    __syncthreads();
    if (t < 32) {
        unsigned v = ws[t];
        for (int o = 16; o > 0; o >>= 1) v += __shfl_down_sync(0xffffffffu, v, o);
        if (t == 0) g_blockCnt[b] = v;
    }
}

// scan 128 block counts; init numPts / ranks / sel state
__global__ void scanK() {
    __shared__ unsigned s[CB];
    int t = threadIdx.x;                 // 128 threads
    unsigned v = g_blockCnt[t];
    s[t] = v;
    __syncthreads();
    for (int off = 1; off < CB; off <<= 1) {
        unsigned x = (t >= off) ? s[t - off] : 0u;
        __syncthreads();
        s[t] += x;
        __syncthreads();
    }
    g_blockOff[t] = s[t] - v;            // exclusive
    if (t == CB - 1) {
        unsigned n = s[CB - 1];
        g_numPts = n;
        unsigned k0 = (n > 0u) ? ((n - 1u) >> 1) : 0u;
        unsigned itp = (n > 0u) ? ((n - 1u) & 1u) : 0u;
        g_interp = itp;
        for (int st = 0; st < 4; st++) {
            g_sel[st].prefix = 0u;
            g_sel[st].rank = (st & 1) ? (k0 + itp) : k0;
        }
    }
}

// order-preserving compaction into xc/yc + fused level-0 y-histogram.
// Fast path when the whole chunk is valid (positions are affine).
__global__ void compactK(const float* __restrict__ ren,
                         const float* __restrict__ pri, int P, int ch) {
    __shared__ unsigned h[2048];
    __shared__ unsigned ws[32];
    int b = blockIdx.x, t = threadIdx.x;
    int lane = t & 31, wid = t >> 5;
    for (int i = t; i < 2048; i += 1024) h[i] = 0u;
    __syncthreads();
    int base0 = b * ch;
    int elems = P - base0; if (elems > ch) elems = ch; if (elems < 0) elems = 0;
    unsigned off = g_blockOff[b];
    unsigned cnt = g_blockCnt[b];

    if ((int)cnt == elems && (off & 3u) == 0u) {
        // -------- fast path: dense chunk, affine positions, float4 I/O ------
        int e4 = elems >> 2;
        const float4* r4 = (const float4*)(ren + base0);
        const float4* p4 = (const float4*)(pri + base0);
        float4* yo = (float4*)(g_yc + off);
        float4* xo = (float4*)(g_xc + off);
        for (int j = t; j < e4; j += 1024) {
            float4 d = r4[j];
            float4 y;
            y.x = invren(d.x); y.y = invren(d.y);
            y.z = invren(d.z); y.w = invren(d.w);
            yo[j] = y;
            xo[j] = p4[j];
            aggAdd(h, ordkey(y.x) >> 21);
            aggAdd(h, ordkey(y.y) >> 21);
            aggAdd(h, ordkey(y.z) >> 21);
            aggAdd(h, ordkey(y.w) >> 21);
        }
        int rem = elems & 3, b4 = e4 << 2;
        if (t < rem) {
            float d = ren[base0 + b4 + t];
            float y = invren(d);
            g_yc[off + b4 + t] = y;
            g_xc[off + b4 + t] = pri[base0 + b4 + t];
            aggAdd(h, ordkey(y) >> 21);
        }
    } else {
        // -------- fallback: ballot-scan order-preserving compaction ---------
        unsigned running = off;
        int waves = ch >> 10;
        for (int w = 0; w < waves; w++) {
            int i = base0 + (w << 10) + t;
            bool m = false; float y = 0.f, x = 0.f;
            if (i < P) {
                float d = ren[i];
                if (maskf(d)) { m = true; y = invren(d); x = pri[i]; }
            }
            unsigned bal = __ballot_sync(0xffffffffu, m);
            unsigned wr = __popc(bal & ((1u << lane) - 1u));
            if (lane == 0) ws[wid] = __popc(bal);
            __syncthreads();
            if (t < 32) {
                unsigned v = ws[t];
                for (int o = 1; o < 32; o <<= 1) {
                    unsigned x2 = __shfl_up_sync(0xffffffffu, v, o);
                    if (lane >= o) v += x2;
                }
                ws[t] = v;                    // inclusive
            }
            __syncthreads();
            unsigned woff = (wid == 0) ? 0u : ws[wid - 1];
            if (m) {
                unsigned pos = running + woff + wr;
                g_yc[pos] = y;
                g_xc[pos] = x;
                aggAdd(h, ordkey(y) >> 21);
            }
            running += ws[31];
            __syncthreads();
        }
    }
    __syncthreads();
    for (int i = t; i < 2048; i += 1024) {
        unsigned c = h[i];
        if (c) atomicAdd(&g_hist[0][i], c);
    }
}

// level-0 histogram of z = |y - med| over dense yc
__global__ void histZeroK(int hIdx) {
    __shared__ unsigned h[2048];
    for (int i = threadIdx.x; i < 2048; i += blockDim.x) h[i] = 0u;
    __syncthreads();
    unsigned n = g_numPts;
    float med = g_med;
    const float4* y4 = (const float4*)g_yc;
    unsigned n4 = n >> 2;
    for (unsigned i = blockIdx.x * blockDim.x + threadIdx.x; i < n4;
         i += gridDim.x * blockDim.x) {
        float4 v = y4[i];
        aggAdd(h, ordkey(fabsf(v.x - med)) >> 21);
        aggAdd(h, ordkey(fabsf(v.y - med)) >> 21);
        aggAdd(h, ordkey(fabsf(v.z - med)) >> 21);
        aggAdd(h, ordkey(fabsf(v.w - med)) >> 21);
    }
    if (blockIdx.x == 0 && threadIdx.x < (n & 3u)) {
        float y = g_yc[(n4 << 2) + threadIdx.x];
        aggAdd(h, ordkey(fabsf(y - med)) >> 21);
    }
    __syncthreads();
    for (int i = threadIdx.x; i < 2048; i += blockDim.x) {
        unsigned c = h[i];
        if (c) atomicAdd(&g_hist[hIdx][i], c);
    }
}

// dual-state histogram pass for levels 1/2 over dense yc
__global__ void histPairK(int mode, int level, int sA, int sB, int hA, int hB) {
    __shared__ unsigned h[2][2048];
    for (int i = threadIdx.x; i < 4096; i += blockDim.x)
        ((unsigned*)h)[i] = 0u;
    __syncthreads();
    unsigned n = g_numPts;
    unsigned pA = g_sel[sA].prefix;
    unsigned pB = g_sel[sB].prefix;
    float med = mode ? g_med : 0.0f;
    const float4* y4 = (const float4*)g_yc;
    unsigned n4 = n >> 2;

#define HP_ONE(yy) do {                                                    \
        float z = mode ? fabsf((yy) - med) : (yy);                         \
        unsigned key = ordkey(z);                                          \
        if (level == 1) {                                                  \
            unsigned top = key >> 21, mid = (key >> 10) & 2047u;           \
            if (top == pA) aggAdd(h[0], mid);                              \
            if (top == pB) aggAdd(h[1], mid);                              \
        } else {                                                           \
            unsigned top = key >> 10, lo = key & 1023u;                    \
            if (top == pA) aggAdd(h[0], lo);                               \
            if (top == pB) aggAdd(h[1], lo);                               \
        }                                                                  \
    } while (0)

    for (unsigned i = blockIdx.x * blockDim.x + threadIdx.x; i < n4;
         i += gridDim.x * blockDim.x) {
        float4 v = y4[i];
        HP_ONE(v.x); HP_ONE(v.y); HP_ONE(v.z); HP_ONE(v.w);
    }
    if (blockIdx.x == 0 && threadIdx.x < (n & 3u)) {
        float y = g_yc[(n4 << 2) + threadIdx.x];
        HP_ONE(y);
    }
#undef HP_ONE
    __syncthreads();
    for (int i = threadIdx.x; i < 2048; i += blockDim.x) {
        unsigned cA = h[0][i];
        if (cA) atomicAdd(&g_hist[hA][i], cA);
        unsigned cB = h[1][i];
        if (cB) atomicAdd(&g_hist[hB][i], cB);
    }
}

// one radix-select step for one state (inside selPairK's single block)
__device__ void selStep(const unsigned* hist, int nbins, int level,
                        int stateIdx, unsigned* ws) {
    int t = threadIdx.x;
    int per = nbins >> 10;               // 2 or 1
    unsigned v0 = hist[t * per];
    unsigned v1 = (per == 2) ? hist[t * per + 1] : 0u;
    unsigned my = v0 + v1;
    unsigned incl = blockScanIncl(my, ws);
    unsigned base = incl - my;
    unsigned rank = g_sel[stateIdx].rank;
    if (my > 0 && rank >= base && rank < incl) {
        unsigned digit, rem;
        if (rank < base + v0) { digit = t * per;     rem = rank - base; }
        else                  { digit = t * per + 1; rem = rank - base - v0; }
        unsigned pfx = g_sel[stateIdx].prefix;
        int bits = (level == 2) ? 10 : 11;
        unsigned np = (pfx << bits) | digit;
        g_sel[stateIdx].prefix = np;
        g_sel[stateIdx].rank = rem;
        if (level == 2) g_medv[stateIdx] = ordval(np);
    }
    __syncthreads();
}

// finalize: 0=none, 1=compute med, 2=compute dyn
__global__ void selPairK(int hA, int hB, int nbins, int level,
                         int sA, int sB, int finalize) {
    __shared__ unsigned ws[32];
    selStep(g_hist[hA], nbins, level, sA, ws);
    selStep(g_hist[hB], nbins, level, sB, ws);
    if (threadIdx.x == 0) {
        if (finalize == 1) {
            g_med = g_interp ? (0.5f * g_medv[0] + 0.5f * g_medv[1]) : g_medv[0];
        } else if (finalize == 2) {
            float mz = g_interp ? (0.5f * g_medv[2] + 0.5f * g_medv[3]) : g_medv[2];
            float dyn = mz * 0.5f;
            if (dyn < 1e-5f) dyn = 0.01f;
            g_dyn = dyn;
        }
    }
}

// sub draws + pair draws + per-iteration scale/shift, all in one kernel
__global__ void genK(unsigned kp0, unsigned kp1, unsigned kp2, unsigned kp3,
                     unsigned ks0, unsigned ks1, unsigned ks2, unsigned ks3) {
    unsigned gid = blockIdx.x * blockDim.x + threadIdx.x;
    unsigned n = g_numPts;
    unsigned span = (n > 0u) ? n : 1u;
    if (gid < SUBN) {
        unsigned hi = rnd_bits(ks0, ks1, gid);
        unsigned lo = rnd_bits(ks2, ks3, gid);
        unsigned p = randint_combine(hi, lo, span);
        g_xs[gid] = g_xc[p];
        g_ys[gid] = g_yc[p];
    }
    if (gid < ITERS) {
        unsigned f0 = 2u * gid, f1 = 2u * gid + 1u;
        unsigned p0 = randint_combine(rnd_bits(kp0, kp1, f0),
                                      rnd_bits(kp2, kp3, f0), span);
        unsigned p1 = randint_combine(rnd_bits(kp0, kp1, f1),
                                      rnd_bits(kp2, kp3, f1), span);
        float x1v = g_xc[p0], x2v = g_xc[p1];
        float y1v = g_yc[p0], y2v = g_yc[p1];
        float s = (y2v - y1v) / (x2v - x1v + 1e-8f);
        g_scales[gid] = s;
        g_shifts[gid] = y1v - s * x1v;
    }
}

#define SUBB 2500
#define ITPB 125
__global__ void countK() {
    __shared__ float sx[SUBB];
    __shared__ float sy[SUBB];
    int sb = blockIdx.x;        // 0..19 sub-chunks
    int ic = blockIdx.y;        // 0..7 iter-chunks
    int t = threadIdx.x;        // 256
    int lane = t & 31;
    int sbase = sb * SUBB;
    for (int j = t; j < SUBB; j += 256) { sx[j] = g_xs[sbase + j]; sy[j] = g_ys[sbase + j]; }
    float dyn = g_dyn;
    __syncthreads();
    for (int it = 0; it < ITPB; it++) {
        int iter = ic * ITPB + it;
        float s = g_scales[iter];
        if (!(s > 0.0f)) continue;       // block-uniform branch
        float tt = g_shifts[iter];
        int c = 0;
        for (int j = t; j < SUBB; j += 256) {
            float r = fabsf(fmaf(s, sx[j], tt) - sy[j]);
            c += (r < dyn) ? 1 : 0;
        }
        for (int o = 16; o > 0; o >>= 1) c += __shfl_down_sync(0xffffffffu, c, o);
        if (lane == 0 && c) atomicAdd(&g_counts[iter], c);
    }
}

__global__ void argmaxK() {
    __shared__ int bv[1024];
    __shared__ int bi[1024];
    int t = threadIdx.x;
    int best = -2, bidx = 0;
    for (int i = t; i < ITERS; i += 1024) {
        int v = (g_scales[i] > 0.0f) ? g_counts[i] : -1;
        if (v > best) { best = v; bidx = i; }
    }
    bv[t] = best; bi[t] = bidx;
    __syncthreads();
    for (int off = 512; off > 0; off >>= 1) {
        if (t < off) {
            if (bv[t + off] > bv[t] ||
                (bv[t + off] == bv[t] && bi[t + off] < bi[t])) {
                bv[t] = bv[t + off]; bi[t] = bi[t + off];
            }
        }
        __syncthreads();
    }
    if (t == 0) {
        int b = bi[0];
        bool valid = bv[0] >= 0;
        float s = valid ? g_scales[b] : 1.0f;
        float tt = valid ? g_shifts[b] : 0.0f;
        if (g_numPts < 10u) { s = 1.0f; tt = 0.0f; }
        g_s = s; g_t = tt;
    }
}

// 4 coalesced waves per block (4096 elems/block)
__global__ void finalK(const float* __restrict__ ren,
                       const float* __restrict__ pri,
                       float* __restrict__ out, int P) {
    int t = threadIdx.x;
    int lane = t & 31, wid = t >> 5;
    __shared__ float ws[32];
    float acc = 0.0f;
    float s = g_s, tt = g_t;
    int base = blockIdx.x * 4096;
#pragma unroll
    for (int w = 0; w < 4; w++) {
        int i = base + (w << 10) + t;
        if (i < P) {
            float d = ren[i];
            float y = invren(d);
            out[1 + i] = y;
            float al = fmaf(s, pri[i], tt);
            out[1 + P + i] = 1.0f / fmaxf(al, 1e-4f);
            if (maskf(d)) acc += fabsf(al - y);
        }
    }
    for (int o = 16; o > 0; o >>= 1) acc += __shfl_down_sync(0xffffffffu, acc, o);
    if (lane == 0) ws[wid] = acc;
    __syncthreads();
    if (t < 32) {
        float v = ws[t];
        for (int o = 16; o > 0; o >>= 1) v += __shfl_down_sync(0xffffffffu, v, o);
        if (t == 0) g_partial[blockIdx.x] = v;
    }
}

__global__ void lossK(float* __restrict__ out, int nPart) {
    __shared__ float sf[1024];
    int t = threadIdx.x;
    float a = 0.0f;
    for (int i = t; i < nPart; i += 1024) a += g_partial[i];
    sf[t] = a;
    __syncthreads();
    for (int off = 512; off > 0; off >>= 1) {
        if (t < off) sf[t] += sf[t + off];
        __syncthreads();
    }
    if (t == 0) {
        unsigned n = g_numPts;
        unsigned dn = (n > 1u) ? n : 1u;
        float l1 = sf[0] / (float)dn;
        float total = 0.5f * l1;
        if (n < 100u) total = 0.0f;
        out[0] = total;
    }
}

// ------------------------------ host ---------------------------------------
static void hsplit(unsigned k0, unsigned k1, unsigned o[4]) {
    unsigned a0, a1, b0, b1;
    tf2x32(k0, k1, 0u, 0u, a0, a1);
    tf2x32(k0, k1, 0u, 1u, b0, b1);
    o[0] = a0; o[1] = a1;
    o[2] = b0; o[3] = b1;
}

extern "C" void kernel_launch(void* const* d_in, const int* in_sizes, int n_in,
                              void* d_out, int out_size) {
    const float* ren = (const float*)d_in[0];
    const float* pri = (const float*)d_in[1];
    float* out = (float*)d_out;
    int P = in_sizes[0];
    int ch = (((P + CB - 1) / CB) + 1023) & ~1023;   // per-block chunk, x1024

    // threefry key chain from seed 42 (partitionable mode)
    unsigned rootSplit[4];
    hsplit(0u, 42u, rootSplit);                 // k_pair, k_sub
    unsigned kp[4], ks[4];
    hsplit(rootSplit[0], rootSplit[1], kp);     // randint subkeys for pairs
    hsplit(rootSplit[2], rootSplit[3], ks);     // randint subkeys for sub

    initK<<<42, 512>>>();
    maskCountK<<<CB, 1024>>>(ren, P, ch);
    scanK<<<1, CB>>>();
    compactK<<<CB, 1024>>>(ren, pri, P, ch);    // + fused L0 y-hist -> g_hist[0]

    // ---- median of y ----
    selPairK<<<1, 1024>>>(0, 0, 2048, 0, 0, 1, 0);
    histPairK<<<528, 256>>>(0, 1, 0, 1, 1, 2);
    selPairK<<<1, 1024>>>(1, 2, 2048, 1, 0, 1, 0);
    histPairK<<<528, 256>>>(0, 2, 0, 1, 3, 4);
    selPairK<<<1, 1024>>>(3, 4, 1024, 2, 0, 1, 1);   // -> g_med

    // ---- median of |y - med| -> dyn ----
    histZeroK<<<528, 256>>>(5);
    selPairK<<<1, 1024>>>(5, 5, 2048, 0, 2, 3, 0);
    histPairK<<<528, 256>>>(1, 1, 2, 3, 6, 7);
    selPairK<<<1, 1024>>>(6, 7, 2048, 1, 2, 3, 0);
    histPairK<<<528, 256>>>(1, 2, 2, 3, 8, 9);
    selPairK<<<1, 1024>>>(8, 9, 1024, 2, 2, 3, 2);   // -> g_dyn

    // ---- RANSAC ----
    genK<<<(SUBN + 255) / 256, 256>>>(kp[0], kp[1], kp[2], kp[3],
                                      ks[0], ks[1], ks[2], ks[3]);
    countK<<<dim3(SUBN / SUBB, ITERS / ITPB), 256>>>();
    argmaxK<<<1, 1024>>>();

    // ---- outputs ----
    int nbf = (P + 4095) / 4096;
    finalK<<<nbf, 1024>>>(ren, pri, out, P);
    lossK<<<1, 1024>>>(out, nbf);
}

// round 17
// speedup vs baseline: 1.7385x; 1.7385x over previous
#include <cuda_runtime.h>
#include <stdint.h>
#include <math.h>

// ---------------------------------------------------------------------------
// DepthPriorLoss — multi-kernel optimized (fast-path compaction, plain atomics).
// Inputs: d_in[0]=rendered_depth f32 [P], d_in[1]=prior_disparity f32 [P].
// Out: out[0]=loss, out[1..P]=target_inv_ren, out[1+P..2P]=prior_metric_depth.
// ---------------------------------------------------------------------------

#define P_MAX (1u << 21)
#define ITERS 1000
#define SUBN  50000
#define CB    128            // compaction blocks (contiguous chunks, order kept)

struct Sel { unsigned prefix; unsigned rank; };

__device__ float    g_xc[P_MAX];     // compacted prior_disparity (masked order)
__device__ float    g_yc[P_MAX];     // compacted target_inv_ren
__device__ unsigned g_blockCnt[CB];
__device__ unsigned g_blockOff[CB];
__device__ unsigned g_numPts;
__device__ unsigned g_interp;
__device__ unsigned g_hist[10][2048];
__device__ Sel      g_sel[4];
__device__ float    g_medv[4];
__device__ float    g_med;
__device__ float    g_dyn;
__device__ float    g_xs[SUBN];
__device__ float    g_ys[SUBN];
__device__ float    g_scales[ITERS];
__device__ float    g_shifts[ITERS];
__device__ int      g_counts[ITERS];
__device__ float    g_s, g_t;
__device__ float    g_partial[1024];

// ---------------------------- Threefry-2x32 --------------------------------
__host__ __device__ __forceinline__
void tf2x32(unsigned k0, unsigned k1, unsigned c0, unsigned c1,
            unsigned& o0, unsigned& o1) {
    unsigned ks2 = k0 ^ k1 ^ 0x1BD11BDAu;
    unsigned x0 = c0 + k0;
    unsigned x1 = c1 + k1;
#define TF_RND(r) { x0 += x1; x1 = (x1 << (r)) | (x1 >> (32 - (r))); x1 ^= x0; }
    TF_RND(13) TF_RND(15) TF_RND(26) TF_RND(6)
    x0 += k1;  x1 += ks2 + 1u;
    TF_RND(17) TF_RND(29) TF_RND(16) TF_RND(24)
    x0 += ks2; x1 += k0 + 2u;
    TF_RND(13) TF_RND(15) TF_RND(26) TF_RND(6)
    x0 += k0;  x1 += k1 + 3u;
    TF_RND(17) TF_RND(29) TF_RND(16) TF_RND(24)
    x0 += k1;  x1 += ks2 + 4u;
    TF_RND(13) TF_RND(15) TF_RND(26) TF_RND(6)
    x0 += ks2; x1 += k0 + 5u;
#undef TF_RND
    o0 = x0; o1 = x1;
}

__device__ __forceinline__ unsigned rnd_bits(unsigned k0, unsigned k1, unsigned f) {
    unsigned o0, o1;
    tf2x32(k0, k1, 0u, f, o0, o1);
    return o0 ^ o1;
}

__device__ __forceinline__ unsigned randint_combine(unsigned hi, unsigned lo,
                                                    unsigned span) {
    unsigned mult = 65536u % span;
    mult = (mult * mult) % span;                       // u32 wrap then mod (lax)
    unsigned off = (hi % span) * mult + (lo % span);   // u32 wrap (lax)
    return off % span;
}

// ------------------------------ helpers ------------------------------------
__device__ __forceinline__ bool maskf(float d) {
    return (d > 0.1f) && (d < 100.0f) && isfinite(d);
}
__device__ __forceinline__ float invren(float d) { return 1.0f / (d + 1e-6f); }

__device__ __forceinline__ unsigned ordkey(float v) {
    unsigned u = __float_as_uint(v);
    return (u & 0x80000000u) ? ~u : (u | 0x80000000u);
}
__device__ __forceinline__ float ordval(unsigned o) {
    unsigned u = (o & 0x80000000u) ? (o & 0x7FFFFFFFu) : ~o;
    return __uint_as_float(u);
}

// block-wide inclusive scan (1024 threads, 2 syncs), ws = smem[32]
__device__ __forceinline__ unsigned blockScanIncl(unsigned v, unsigned* ws) {
    int lane = threadIdx.x & 31, wid = threadIdx.x >> 5;
    for (int o = 1; o < 32; o <<= 1) {
        unsigned x = __shfl_up_sync(0xffffffffu, v, o);
        if (lane >= o) v += x;
    }
    if (lane == 31) ws[wid] = v;
    __syncthreads();
    if (wid == 0) {
        unsigned s = ws[lane];
        for (int o = 1; o < 32; o <<= 1) {
            unsigned x = __shfl_up_sync(0xffffffffu, s, o);
            if (lane >= o) s += x;
        }
        ws[lane] = s;
    }
    __syncthreads();
    return v + (wid ? ws[wid - 1] : 0u);
}

// ------------------------------ kernels ------------------------------------
__global__ void initK() {
    int i = blockIdx.x * blockDim.x + threadIdx.x;
    if (i < 10 * 2048) ((unsigned*)g_hist)[i] = 0u;
    if (i < ITERS) g_counts[i] = 0;
}

// per-block mask counts over contiguous chunks (float4)
__global__ void maskCountK(const float* __restrict__ ren, int P, int ch) {
    int b = blockIdx.x, t = threadIdx.x;
    int lane = t & 31, wid = t >> 5;
    __shared__ unsigned ws[32];
    int base0 = b * ch;
    int elems = P - base0; if (elems > ch) elems = ch; if (elems < 0) elems = 0;
    int e4 = elems >> 2;
    const float4* r4 = (const float4*)(ren + base0);
    unsigned c = 0;
    for (int j = t; j < e4; j += 1024) {
        float4 d = r4[j];
        c += (maskf(d.x) ? 1u : 0u) + (maskf(d.y) ? 1u : 0u)
           + (maskf(d.z) ? 1u : 0u) + (maskf(d.w) ? 1u : 0u);
    }
    if (t < (elems & 3) && maskf(ren[base0 + (e4 << 2) + t])) c++;
    for (int o = 16; o > 0; o >>= 1) c += __shfl_down_sync(0xffffffffu, c, o);
    if (lane == 0) ws[wid] = c;
    __syncthreads();
    if (t < 32) {
        unsigned v = ws[t];
        for (int o = 16; o > 0; o >>= 1) v += __shfl_down_sync(0xffffffffu, v, o);
        if (t == 0) g_blockCnt[b] = v;
    }
}

// scan 128 block counts; init numPts / ranks / sel state
__global__ void scanK() {
    __shared__ unsigned s[CB];
    int t = threadIdx.x;                 // 128 threads
    unsigned v = g_blockCnt[t];
    s[t] = v;
    __syncthreads();
    for (int off = 1; off < CB; off <<= 1) {
        unsigned x = (t >= off) ? s[t - off] : 0u;
        __syncthreads();
        s[t] += x;
        __syncthreads();
    }
    g_blockOff[t] = s[t] - v;            // exclusive
    if (t == CB - 1) {
        unsigned n = s[CB - 1];
        g_numPts = n;
        unsigned k0 = (n > 0u) ? ((n - 1u) >> 1) : 0u;
        unsigned itp = (n > 0u) ? ((n - 1u) & 1u) : 0u;
        g_interp = itp;
        for (int st = 0; st < 4; st++) {
            g_sel[st].prefix = 0u;
            g_sel[st].rank = (st & 1) ? (k0 + itp) : k0;
        }
    }
}

// order-preserving compaction into xc/yc + fused level-0 y-histogram.
// Fast path when the whole chunk is valid (positions are affine).
__global__ void compactK(const float* __restrict__ ren,
                         const float* __restrict__ pri, int P, int ch) {
    __shared__ unsigned h[2048];
    __shared__ unsigned ws[32];
    int b = blockIdx.x, t = threadIdx.x;
    int lane = t & 31, wid = t >> 5;
    for (int i = t; i < 2048; i += 1024) h[i] = 0u;
    __syncthreads();
    int base0 = b * ch;
    int elems = P - base0; if (elems > ch) elems = ch; if (elems < 0) elems = 0;
    unsigned off = g_blockOff[b];
    unsigned cnt = g_blockCnt[b];

    if ((int)cnt == elems && (off & 3u) == 0u) {
        // -------- fast path: dense chunk, affine positions, float4 I/O ------
        int e4 = elems >> 2;
        const float4* r4 = (const float4*)(ren + base0);
        const float4* p4 = (const float4*)(pri + base0);
        float4* yo = (float4*)(g_yc + off);
        float4* xo = (float4*)(g_xc + off);
        for (int j = t; j < e4; j += 1024) {
            float4 d = r4[j];
            float4 y;
            y.x = invren(d.x); y.y = invren(d.y);
            y.z = invren(d.z); y.w = invren(d.w);
            yo[j] = y;
            xo[j] = p4[j];
            atomicAdd(&h[ordkey(y.x) >> 21], 1u);
            atomicAdd(&h[ordkey(y.y) >> 21], 1u);
            atomicAdd(&h[ordkey(y.z) >> 21], 1u);
            atomicAdd(&h[ordkey(y.w) >> 21], 1u);
        }
        int rem = elems & 3, b4 = e4 << 2;
        if (t < rem) {
            float d = ren[base0 + b4 + t];
            float y = invren(d);
            g_yc[off + b4 + t] = y;
            g_xc[off + b4 + t] = pri[base0 + b4 + t];
            atomicAdd(&h[ordkey(y) >> 21], 1u);
        }
    } else {
        // -------- fallback: ballot-scan order-preserving compaction ---------
        unsigned running = off;
        int waves = ch >> 10;
        for (int w = 0; w < waves; w++) {
            int i = base0 + (w << 10) + t;
            bool m = false; float y = 0.f, x = 0.f;
            if (i < P) {
                float d = ren[i];
                if (maskf(d)) { m = true; y = invren(d); x = pri[i]; }
            }
            unsigned bal = __ballot_sync(0xffffffffu, m);
            unsigned wr = __popc(bal & ((1u << lane) - 1u));
            if (lane == 0) ws[wid] = __popc(bal);
            __syncthreads();
            if (t < 32) {
                unsigned v = ws[t];
                for (int o = 1; o < 32; o <<= 1) {
                    unsigned x2 = __shfl_up_sync(0xffffffffu, v, o);
                    if (lane >= o) v += x2;
                }
                ws[t] = v;                    // inclusive
            }
            __syncthreads();
            unsigned woff = (wid == 0) ? 0u : ws[wid - 1];
            if (m) {
                unsigned pos = running + woff + wr;
                g_yc[pos] = y;
                g_xc[pos] = x;
                atomicAdd(&h[ordkey(y) >> 21], 1u);
            }
            running += ws[31];
            __syncthreads();
        }
    }
    __syncthreads();
    for (int i = t; i < 2048; i += 1024) {
        unsigned c = h[i];
        if (c) atomicAdd(&g_hist[0][i], c);
    }
}

// level-0 histogram of z = |y - med| over dense yc
__global__ void histZeroK(int hIdx) {
    __shared__ unsigned h[2048];
    for (int i = threadIdx.x; i < 2048; i += blockDim.x) h[i] = 0u;
    __syncthreads();
    unsigned n = g_numPts;
    float med = g_med;
    const float4* y4 = (const float4*)g_yc;
    unsigned n4 = n >> 2;
    for (unsigned i = blockIdx.x * blockDim.x + threadIdx.x; i < n4;
         i += gridDim.x * blockDim.x) {
        float4 v = y4[i];
        atomicAdd(&h[ordkey(fabsf(v.x - med)) >> 21], 1u);
        atomicAdd(&h[ordkey(fabsf(v.y - med)) >> 21], 1u);
        atomicAdd(&h[ordkey(fabsf(v.z - med)) >> 21], 1u);
        atomicAdd(&h[ordkey(fabsf(v.w - med)) >> 21], 1u);
    }
    if (blockIdx.x == 0 && threadIdx.x < (n & 3u)) {
        float y = g_yc[(n4 << 2) + threadIdx.x];
        atomicAdd(&h[ordkey(fabsf(y - med)) >> 21], 1u);
    }
    __syncthreads();
    for (int i = threadIdx.x; i < 2048; i += blockDim.x) {
        unsigned c = h[i];
        if (c) atomicAdd(&g_hist[hIdx][i], c);
    }
}

// dual-state histogram pass for levels 1/2 over dense yc
__global__ void histPairK(int mode, int level, int sA, int sB, int hA, int hB) {
    __shared__ unsigned h[2][2048];
    for (int i = threadIdx.x; i < 4096; i += blockDim.x)
        ((unsigned*)h)[i] = 0u;
    __syncthreads();
    unsigned n = g_numPts;
    unsigned pA = g_sel[sA].prefix;
    unsigned pB = g_sel[sB].prefix;
    float med = mode ? g_med : 0.0f;
    const float4* y4 = (const float4*)g_yc;
    unsigned n4 = n >> 2;

#define HP_ONE(yy) do {                                                    \
        float z = mode ? fabsf((yy) - med) : (yy);                         \
        unsigned key = ordkey(z);                                          \
        if (level == 1) {                                                  \
            unsigned top = key >> 21, mid = (key >> 10) & 2047u;           \
            if (top == pA) atomicAdd(&h[0][mid], 1u);                      \
            if (top == pB) atomicAdd(&h[1][mid], 1u);                      \
        } else {                                                           \
            unsigned top = key >> 10, lo = key & 1023u;                    \
            if (top == pA) atomicAdd(&h[0][lo], 1u);                       \
            if (top == pB) atomicAdd(&h[1][lo], 1u);                       \
        }                                                                  \
    } while (0)

    for (unsigned i = blockIdx.x * blockDim.x + threadIdx.x; i < n4;
         i += gridDim.x * blockDim.x) {
        float4 v = y4[i];
        HP_ONE(v.x); HP_ONE(v.y); HP_ONE(v.z); HP_ONE(v.w);
    }
    if (blockIdx.x == 0 && threadIdx.x < (n & 3u)) {
        float y = g_yc[(n4 << 2) + threadIdx.x];
        HP_ONE(y);
    }
#undef HP_ONE
    __syncthreads();
    for (int i = threadIdx.x; i < 2048; i += blockDim.x) {
        unsigned cA = h[0][i];
        if (cA) atomicAdd(&g_hist[hA][i], cA);
        unsigned cB = h[1][i];
        if (cB) atomicAdd(&g_hist[hB][i], cB);
    }
}

// one radix-select step for one state (inside selPairK's single block)
__device__ void selStep(const unsigned* hist, int nbins, int level,
                        int stateIdx, unsigned* ws) {
    int t = threadIdx.x;
    int per = nbins >> 10;               // 2 or 1
    unsigned v0 = hist[t * per];
    unsigned v1 = (per == 2) ? hist[t * per + 1] : 0u;
    unsigned my = v0 + v1;
    unsigned incl = blockScanIncl(my, ws);
    unsigned base = incl - my;
    unsigned rank = g_sel[stateIdx].rank;
    if (my > 0 && rank >= base && rank < incl) {
        unsigned digit, rem;
        if (rank < base + v0) { digit = t * per;     rem = rank - base; }
        else                  { digit = t * per + 1; rem = rank - base - v0; }
        unsigned pfx = g_sel[stateIdx].prefix;
        int bits = (level == 2) ? 10 : 11;
        unsigned np = (pfx << bits) | digit;
        g_sel[stateIdx].prefix = np;
        g_sel[stateIdx].rank = rem;
        if (level == 2) g_medv[stateIdx] = ordval(np);
    }
    __syncthreads();
}

// finalize: 0=none, 1=compute med, 2=compute dyn
__global__ void selPairK(int hA, int hB, int nbins, int level,
                         int sA, int sB, int finalize) {
    __shared__ unsigned ws[32];
    selStep(g_hist[hA], nbins, level, sA, ws);
    selStep(g_hist[hB], nbins, level, sB, ws);
    if (threadIdx.x == 0) {
        if (finalize == 1) {
            g_med = g_interp ? (0.5f * g_medv[0] + 0.5f * g_medv[1]) : g_medv[0];
        } else if (finalize == 2) {
            float mz = g_interp ? (0.5f * g_medv[2] + 0.5f * g_medv[3]) : g_medv[2];
            float dyn = mz * 0.5f;
            if (dyn < 1e-5f) dyn = 0.01f;
            g_dyn = dyn;
        }
    }
}

// sub draws + pair draws + per-iteration scale/shift, all in one kernel
__global__ void genK(unsigned kp0, unsigned kp1, unsigned kp2, unsigned kp3,
                     unsigned ks0, unsigned ks1, unsigned ks2, unsigned ks3) {
    unsigned gid = blockIdx.x * blockDim.x + threadIdx.x;
    unsigned n = g_numPts;
    unsigned span = (n > 0u) ? n : 1u;
    if (gid < SUBN) {
        unsigned hi = rnd_bits(ks0, ks1, gid);
        unsigned lo = rnd_bits(ks2, ks3, gid);
        unsigned p = randint_combine(hi, lo, span);
        g_xs[gid] = g_xc[p];
        g_ys[gid] = g_yc[p];
    }
    if (gid < ITERS) {
        unsigned f0 = 2u * gid, f1 = 2u * gid + 1u;
        unsigned p0 = randint_combine(rnd_bits(kp0, kp1, f0),
                                      rnd_bits(kp2, kp3, f0), span);
        unsigned p1 = randint_combine(rnd_bits(kp0, kp1, f1),
                                      rnd_bits(kp2, kp3, f1), span);
        float x1v = g_xc[p0], x2v = g_xc[p1];
        float y1v = g_yc[p0], y2v = g_yc[p1];
        float s = (y2v - y1v) / (x2v - x1v + 1e-8f);
        g_scales[gid] = s;
        g_shifts[gid] = y1v - s * x1v;
    }
}

#define SUBB 2500
#define ITPB 125
__global__ void countK() {
    __shared__ float sx[SUBB];
    __shared__ float sy[SUBB];
    int sb = blockIdx.x;        // 0..19 sub-chunks
    int ic = blockIdx.y;        // 0..7 iter-chunks
    int t = threadIdx.x;        // 256
    int lane = t & 31;
    int sbase = sb * SUBB;
    for (int j = t; j < SUBB; j += 256) { sx[j] = g_xs[sbase + j]; sy[j] = g_ys[sbase + j]; }
    float dyn = g_dyn;
    __syncthreads();
    for (int it = 0; it < ITPB; it++) {
        int iter = ic * ITPB + it;
        float s = g_scales[iter];
        if (!(s > 0.0f)) continue;       // block-uniform branch
        float tt = g_shifts[iter];
        int c = 0;
        for (int j = t; j < SUBB; j += 256) {
            float r = fabsf(fmaf(s, sx[j], tt) - sy[j]);
            c += (r < dyn) ? 1 : 0;
        }
        for (int o = 16; o > 0; o >>= 1) c += __shfl_down_sync(0xffffffffu, c, o);
        if (lane == 0 && c) atomicAdd(&g_counts[iter], c);
    }
}

__global__ void argmaxK() {
    __shared__ int bv[1024];
    __shared__ int bi[1024];
    int t = threadIdx.x;
    int best = -2, bidx = 0;
    for (int i = t; i < ITERS; i += 1024) {
        int v = (g_scales[i] > 0.0f) ? g_counts[i] : -1;
        if (v > best) { best = v; bidx = i; }
    }
    bv[t] = best; bi[t] = bidx;
    __syncthreads();
    for (int off = 512; off > 0; off >>= 1) {
        if (t < off) {
            if (bv[t + off] > bv[t] ||
                (bv[t + off] == bv[t] && bi[t + off] < bi[t])) {
                bv[t] = bv[t + off]; bi[t] = bi[t + off];
            }
        }
        __syncthreads();
    }
    if (t == 0) {
        int b = bi[0];
        bool valid = bv[0] >= 0;
        float s = valid ? g_scales[b] : 1.0f;
        float tt = valid ? g_shifts[b] : 0.0f;
        if (g_numPts < 10u) { s = 1.0f; tt = 0.0f; }
        g_s = s; g_t = tt;
    }
}

// 4 coalesced waves per block (4096 elems/block)
__global__ void finalK(const float* __restrict__ ren,
                       const float* __restrict__ pri,
                       float* __restrict__ out, int P) {
    int t = threadIdx.x;
    int lane = t & 31, wid = t >> 5;
    __shared__ float ws[32];
    float acc = 0.0f;
    float s = g_s, tt = g_t;
    int base = blockIdx.x * 4096;
#pragma unroll
    for (int w = 0; w < 4; w++) {
        int i = base + (w << 10) + t;
        if (i < P) {
            float d = ren[i];
            float y = invren(d);
            out[1 + i] = y;
            float al = fmaf(s, pri[i], tt);
            out[1 + P + i] = 1.0f / fmaxf(al, 1e-4f);
            if (maskf(d)) acc += fabsf(al - y);
        }
    }
    for (int o = 16; o > 0; o >>= 1) acc += __shfl_down_sync(0xffffffffu, acc, o);
    if (lane == 0) ws[wid] = acc;
    __syncthreads();
    if (t < 32) {
        float v = ws[t];
        for (int o = 16; o > 0; o >>= 1) v += __shfl_down_sync(0xffffffffu, v, o);
        if (t == 0) g_partial[blockIdx.x] = v;
    }
}

__global__ void lossK(float* __restrict__ out, int nPart) {
    __shared__ float sf[1024];
    int t = threadIdx.x;
    float a = 0.0f;
    for (int i = t; i < nPart; i += 1024) a += g_partial[i];
    sf[t] = a;
    __syncthreads();
    for (int off = 512; off > 0; off >>= 1) {
        if (t < off) sf[t] += sf[t + off];
        __syncthreads();
    }
    if (t == 0) {
        unsigned n = g_numPts;
        unsigned dn = (n > 1u) ? n : 1u;
        float l1 = sf[0] / (float)dn;
        float total = 0.5f * l1;
        if (n < 100u) total = 0.0f;
        out[0] = total;
    }
}

// ------------------------------ host ---------------------------------------
static void hsplit(unsigned k0, unsigned k1, unsigned o[4]) {
    unsigned a0, a1, b0, b1;
    tf2x32(k0, k1, 0u, 0u, a0, a1);
    tf2x32(k0, k1, 0u, 1u, b0, b1);
    o[0] = a0; o[1] = a1;
    o[2] = b0; o[3] = b1;
}

extern "C" void kernel_launch(void* const* d_in, const int* in_sizes, int n_in,
                              void* d_out, int out_size) {
    const float* ren = (const float*)d_in[0];
    const float* pri = (const float*)d_in[1];
    float* out = (float*)d_out;
    int P = in_sizes[0];
    int ch = (((P + CB - 1) / CB) + 1023) & ~1023;   // per-block chunk, x1024

    // threefry key chain from seed 42 (partitionable mode)
    unsigned rootSplit[4];
    hsplit(0u, 42u, rootSplit);                 // k_pair, k_sub
    unsigned kp[4], ks[4];
    hsplit(rootSplit[0], rootSplit[1], kp);     // randint subkeys for pairs
    hsplit(rootSplit[2], rootSplit[3], ks);     // randint subkeys for sub

    initK<<<42, 512>>>();
    maskCountK<<<CB, 1024>>>(ren, P, ch);
    scanK<<<1, CB>>>();
    compactK<<<CB, 1024>>>(ren, pri, P, ch);    // + fused L0 y-hist -> g_hist[0]

    // ---- median of y ----
    selPairK<<<1, 1024>>>(0, 0, 2048, 0, 0, 1, 0);
    histPairK<<<528, 256>>>(0, 1, 0, 1, 1, 2);
    selPairK<<<1, 1024>>>(1, 2, 2048, 1, 0, 1, 0);
    histPairK<<<528, 256>>>(0, 2, 0, 1, 3, 4);
    selPairK<<<1, 1024>>>(3, 4, 1024, 2, 0, 1, 1);   // -> g_med

    // ---- median of |y - med| -> dyn ----
    histZeroK<<<528, 256>>>(5);
    selPairK<<<1, 1024>>>(5, 5, 2048, 0, 2, 3, 0);
    histPairK<<<528, 256>>>(1, 1, 2, 3, 6, 7);
    selPairK<<<1, 1024>>>(6, 7, 2048, 1, 2, 3, 0);
    histPairK<<<528, 256>>>(1, 2, 2, 3, 8, 9);
    selPairK<<<1, 1024>>>(8, 9, 1024, 2, 2, 3, 2);   // -> g_dyn

    // ---- RANSAC ----
    genK<<<(SUBN + 255) / 256, 256>>>(kp[0], kp[1], kp[2], kp[3],
                                      ks[0], ks[1], ks[2], ks[3]);
    countK<<<dim3(SUBN / SUBB, ITERS / ITPB), 256>>>();
    argmaxK<<<1, 1024>>>();

    // ---- outputs ----
    int nbf = (P + 4095) / 4096;
    finalK<<<nbf, 1024>>>(ren, pri, out, P);
    lossK<<<1, 1024>>>(out, nbf);
}